// round 6
// baseline (speedup 1.0000x reference)
#include <cuda_runtime.h>
#include <cuda_bf16.h>
#include <cstdint>

// Problem dims
constexpr int kB  = 16;
constexpr int kN  = 128;
constexpr int kC  = 512;
constexpr int kH  = 8;
constexpr int kR  = 17;
constexpr int kHD = 64;
constexpr int kBN = kB * kN;    // 2048
constexpr int kKp = 3 * kC;     // 1536 split-K' (c contraction)
constexpr int kKq = 3 * kHD;    // 192 split-K' (d contraction, qk)
constexpr int kKm = 3 * kN;     // 384 split-K' (m contraction, av)

// Scratch (device globals; no allocations allowed)
__device__ float g_S[kB * kH * kN * kN]; // 8 MB  (pre-scaled by 0.125)
__device__ int   g_mask_mode;
__device__ __nv_bfloat16 g_Ax[kBN * kKp];        // x hi|lo|hi
__device__ __nv_bfloat16 g_Bqkv[kKp * kKp];      // [q_w;kv_w] hi|hi|lo
__device__ __nv_bfloat16 g_Bproj[kC * kKp];      // proj_w hi|hi|lo
__device__ __nv_bfloat16 g_AO[kBN * kKp];        // O hi|lo|hi (from av epilogue)
__device__ __nv_bfloat16 g_qbf[kB * kH * kN * kKq]; // q hi|lo|hi per (b,h)
__device__ __nv_bfloat16 g_kbf[kB * kH * kN * kKq]; // k hi|hi|lo per (b,h)
__device__ __nv_bfloat16 g_W3[kB * kH * kN * kKm];  // W hi|lo|hi: [bh][n][384]
__device__ __nv_bfloat16 g_yv3[kB * kH * kHD * kKm];// yv hi|hi|lo: [bh][d][384]

__device__ __forceinline__ float neg_inf() { return __int_as_float(0xFF800000); }

// ===================== baseline-PTX helpers =====================
__device__ __forceinline__ uint32_t smem_u32(const void* p) {
    uint32_t a;
    asm("{ .reg .u64 t; cvta.to.shared.u64 t, %1; cvt.u32.u64 %0, t; }"
        : "=r"(a) : "l"(p));
    return a;
}
__device__ __forceinline__ void cp_async16(uint32_t saddr, const void* gaddr) {
    asm volatile("cp.async.cg.shared.global [%0], [%1], 16;"
                 :: "r"(saddr), "l"(gaddr) : "memory");
}
__device__ __forceinline__ void cp_commit() {
    asm volatile("cp.async.commit_group;" ::: "memory");
}
__device__ __forceinline__ void cp_wait0() {
    asm volatile("cp.async.wait_group 0;" ::: "memory");
}
__device__ __forceinline__ void ldsm_x4(uint32_t* r, uint32_t addr) {
    asm volatile("ldmatrix.sync.aligned.m8n8.x4.shared.b16 {%0,%1,%2,%3}, [%4];"
                 : "=r"(r[0]), "=r"(r[1]), "=r"(r[2]), "=r"(r[3]) : "r"(addr));
}
__device__ __forceinline__ void mma16816(float* d, const uint32_t* a, const uint32_t* b) {
    asm volatile("mma.sync.aligned.m16n8k16.row.col.f32.bf16.bf16.f32 "
                 "{%0,%1,%2,%3}, {%4,%5,%6,%7}, {%8,%9}, {%0,%1,%2,%3};"
                 : "+f"(d[0]), "+f"(d[1]), "+f"(d[2]), "+f"(d[3])
                 : "r"(a[0]), "r"(a[1]), "r"(a[2]), "r"(a[3]),
                   "r"(b[0]), "r"(b[1]));
}
__device__ __forceinline__ uint32_t pack_bf2(__nv_bfloat16 lo, __nv_bfloat16 hi) {
    return ((uint32_t)__bfloat16_as_ushort(hi) << 16) | __bfloat16_as_ushort(lo);
}

// ===================== fused converts + mask probe =====================
__global__ __launch_bounds__(128) void convert_all_kernel(
    const float* __restrict__ x, const float* __restrict__ q_w,
    const float* __restrict__ kv_w, const float* __restrict__ proj_w,
    const void* __restrict__ mask,
    __nv_bfloat16* __restrict__ Ax, __nv_bfloat16* __restrict__ Bqkv,
    __nv_bfloat16* __restrict__ Bproj)
{
    const int rb = blockIdx.x;
    if (rb == 4096) {
        __shared__ int s_not_i32, s_not_f32;
        if (threadIdx.x == 0) { s_not_i32 = 0; s_not_f32 = 0; }
        __syncthreads();
        const unsigned int* w = (const unsigned int*)mask;
        int bad_i = 0, bad_f = 0;
        for (int i = threadIdx.x; i < 544; i += 128) {
            unsigned int v = w[i];
            if (v > 1u) bad_i = 1;
            if (v != 0u && v != 0x3F800000u) bad_f = 1;
        }
        if (bad_i) atomicOr(&s_not_i32, 1);
        if (bad_f) atomicOr(&s_not_f32, 1);
        __syncthreads();
        if (threadIdx.x == 0)
            g_mask_mode = (!s_not_i32) ? 0 : ((!s_not_f32) ? 1 : 2);
        return;
    }
    const float* src;
    __nv_bfloat16* dst;
    bool aSide;
    if (rb < 2048)      { src = x + (size_t)rb * kC;             dst = Ax + (size_t)rb * kKp;           aSide = true;  }
    else if (rb < 2560) { int r = rb - 2048; src = q_w + (size_t)r * kC;    dst = Bqkv + (size_t)r * kKp;        aSide = false; }
    else if (rb < 3584) { int r = rb - 2560; src = kv_w + (size_t)r * kC;   dst = Bqkv + (size_t)(kC + r) * kKp; aSide = false; }
    else                { int r = rb - 3584; src = proj_w + (size_t)r * kC; dst = Bproj + (size_t)r * kKp;       aSide = false; }

    const int j0 = threadIdx.x * 4;
    float4 v = *(const float4*)&src[j0];
    float f[4] = {v.x, v.y, v.z, v.w};
    __nv_bfloat16 hi[4], lo[4];
#pragma unroll
    for (int t = 0; t < 4; t++) {
        hi[t] = __float2bfloat16(f[t]);
        lo[t] = __float2bfloat16(f[t] - __bfloat162float(hi[t]));
    }
    uint32_t hp0 = pack_bf2(hi[0], hi[1]), hp1 = pack_bf2(hi[2], hi[3]);
    uint32_t lp0 = pack_bf2(lo[0], lo[1]), lp1 = pack_bf2(lo[2], lo[3]);
    uint32_t* d0 = (uint32_t*)(dst + j0);
    uint32_t* d1 = (uint32_t*)(dst + kC + j0);
    uint32_t* d2 = (uint32_t*)(dst + 2 * kC + j0);
    d0[0] = hp0; d0[1] = hp1;
    if (aSide) { d1[0] = lp0; d1[1] = lp1; d2[0] = hp0; d2[1] = hp1; }
    else       { d1[0] = hp0; d1[1] = hp1; d2[0] = lp0; d2[1] = lp1; }
}

// ===================== templated mma.sync bf16 GEMM =====================
// MODE 0: C0/C1 fp32 split-column output (+bias)
// MODE 1: qkv epilogue -> qbf/kbf triples + yv3 triple ([bh][d][384])
// MODE 2: per-(b,h) qk: S = 0.125 * q@k^T
template<int KBYTES, int NITER, int MODE>
__global__ __launch_bounds__(256) void mma_gemm_t(
    const __nv_bfloat16* __restrict__ A,
    const __nv_bfloat16* __restrict__ Bw,
    float* __restrict__ C0, float* __restrict__ C1,
    const float* __restrict__ bias, int split, int ld0, int ld1,
    __nv_bfloat16* __restrict__ qbf, __nv_bfloat16* __restrict__ kbf,
    __nv_bfloat16* __restrict__ yv3)
{
    __shared__ __align__(16) char smem[2][16384];
    const int tid = threadIdx.x;
    const int wid = tid >> 5, lane = tid & 31;
    const int warp_m = wid >> 1, warp_n = wid & 1;

    int m0, n0;
    const char *Ag, *Bg;
    if (MODE == 2) {
        const size_t off = (size_t)blockIdx.x * 128 * KBYTES;
        Ag = (const char*)A + off;
        Bg = (const char*)Bw + off;
        m0 = 0; n0 = 0;
    } else {
        m0 = blockIdx.y * 128; n0 = blockIdx.x * 128;
        Ag = (const char*)A  + (size_t)m0 * KBYTES;
        Bg = (const char*)Bw + (size_t)n0 * KBYTES;
    }

    const int lr = tid >> 2, lc = tid & 3;
    const uint32_t lso  = (uint32_t)(lr * 64 + ((lc ^ (lr & 3)) << 4));
    const uint32_t lso2 = (uint32_t)((lr + 64) * 64 + ((lc ^ ((lr + 64) & 3)) << 4));
    uint32_t sbase = smem_u32(&smem[0][0]);

    auto stage_load = [&](int st, int k0b) {
        uint32_t sA = sbase + st * 16384;
        uint32_t sB = sA + 8192;
        const char* a0 = Ag + (size_t)lr * KBYTES + k0b + lc * 16;
        const char* b0 = Bg + (size_t)lr * KBYTES + k0b + lc * 16;
        cp_async16(sA + lso,  a0);
        cp_async16(sB + lso,  b0);
        cp_async16(sA + lso2, a0 + (size_t)64 * KBYTES);
        cp_async16(sB + lso2, b0 + (size_t)64 * KBYTES);
    };

    float acc[2][8][4];
#pragma unroll
    for (int i = 0; i < 2; i++)
#pragma unroll
        for (int j = 0; j < 8; j++)
#pragma unroll
            for (int t = 0; t < 4; t++) acc[i][j][t] = 0.f;

    stage_load(0, 0);
    cp_commit();

    const int a_row = warp_m * 32 + (lane & 15);
    const int a_chsel = lane >> 4;
    const int b_mi = lane >> 3;
    const int b_row = warp_n * 64 + ((b_mi >> 1) << 3) + (lane & 7);
    const int b_chsel = b_mi & 1;

    for (int it = 0; it < NITER; it++) {
        cp_wait0();
        __syncthreads();
        if (it + 1 < NITER) { stage_load((it + 1) & 1, (it + 1) * 64); cp_commit(); }

        const uint32_t sA = sbase + (it & 1) * 16384;
        const uint32_t sB = sA + 8192;
#pragma unroll
        for (int kk = 0; kk < 2; kk++) {
            uint32_t a[2][4];
#pragma unroll
            for (int i = 0; i < 2; i++) {
                int r = a_row + i * 16;
                int ch = 2 * kk + a_chsel;
                ldsm_x4(a[i], sA + r * 64 + ((ch ^ (r & 3)) << 4));
            }
            uint32_t b[8][2];
#pragma unroll
            for (int g = 0; g < 4; g++) {
                int r = b_row + g * 16;
                int ch = 2 * kk + b_chsel;
                uint32_t rr[4];
                ldsm_x4(rr, sB + r * 64 + ((ch ^ (r & 3)) << 4));
                b[2 * g][0] = rr[0]; b[2 * g][1] = rr[1];
                b[2 * g + 1][0] = rr[2]; b[2 * g + 1][1] = rr[3];
            }
#pragma unroll
            for (int i = 0; i < 2; i++)
#pragma unroll
                for (int j = 0; j < 8; j++)
                    mma16816(acc[i][j], a[i], b[j]);
        }
        __syncthreads();
    }

    const int gq = lane >> 2, t4 = lane & 3;

    if (MODE == 2) {
        float* Sp = C0 + (size_t)blockIdx.x * kN * kN;
#pragma unroll
        for (int i = 0; i < 2; i++) {
#pragma unroll
            for (int j = 0; j < 8; j++) {
                int col = warp_n * 64 + j * 8 + t4 * 2;
                int r0 = warp_m * 32 + i * 16 + gq;
                *(float2*)&Sp[(size_t)r0 * kN + col] =
                    make_float2(acc[i][j][0] * 0.125f, acc[i][j][1] * 0.125f);
                *(float2*)&Sp[(size_t)(r0 + 8) * kN + col] =
                    make_float2(acc[i][j][2] * 0.125f, acc[i][j][3] * 0.125f);
            }
        }
        return;
    }

    if (MODE == 1) {
        auto emit = [&](int row, int colg, float f0, float f1) {
            if (colg < 1024) {
                const bool isQ = colg < 512;
                const int c = isQ ? colg : colg - 512;
                const int h = c >> 6, d = c & 63;
                __nv_bfloat16 h0 = __float2bfloat16(f0);
                __nv_bfloat16 h1 = __float2bfloat16(f1);
                __nv_bfloat16 l0 = __float2bfloat16(f0 - __bfloat162float(h0));
                __nv_bfloat16 l1 = __float2bfloat16(f1 - __bfloat162float(h1));
                uint32_t hp = pack_bf2(h0, h1);
                uint32_t lp = pack_bf2(l0, l1);
                const int bb = row >> 7, nn = row & 127;
                __nv_bfloat16* base = (isQ ? qbf : kbf)
                    + ((size_t)((bb * kH + h) * kN + nn)) * kKq + d;
                *(uint32_t*)(base)       = hp;
                *(uint32_t*)(base + 64)  = isQ ? lp : hp;
                *(uint32_t*)(base + 128) = isQ ? hp : lp;
            } else {
                // yv -> yv3 triple (hi|hi|lo), layout [bh][d][384m], row=(b,m)
                const int c = colg - 1024;
                const int h = c >> 6, d = c & 63;
                const int bb = row >> 7, m = row & 127;
                __nv_bfloat16* b0 = yv3
                    + ((size_t)((bb * kH + h) * kHD + d)) * kKm + m;
                __nv_bfloat16 h0 = __float2bfloat16(f0);
                __nv_bfloat16 l0 = __float2bfloat16(f0 - __bfloat162float(h0));
                b0[0] = h0; b0[128] = h0; b0[256] = l0;
                __nv_bfloat16* b1 = b0 + kKm;  // d+1 row
                __nv_bfloat16 h1 = __float2bfloat16(f1);
                __nv_bfloat16 l1 = __float2bfloat16(f1 - __bfloat162float(h1));
                b1[0] = h1; b1[128] = h1; b1[256] = l1;
            }
        };
#pragma unroll
        for (int i = 0; i < 2; i++) {
#pragma unroll
            for (int j = 0; j < 8; j++) {
                int colg = n0 + warp_n * 64 + j * 8 + t4 * 2;
                int row0 = m0 + warp_m * 32 + i * 16 + gq;
                emit(row0,     colg, acc[i][j][0], acc[i][j][1]);
                emit(row0 + 8, colg, acc[i][j][2], acc[i][j][3]);
            }
        }
        return;
    }

    // MODE 0
#pragma unroll
    for (int i = 0; i < 2; i++) {
#pragma unroll
        for (int j = 0; j < 8; j++) {
            int colg = n0 + warp_n * 64 + j * 8 + t4 * 2;
            float bz0 = bias ? bias[colg]     : 0.f;
            float bz1 = bias ? bias[colg + 1] : 0.f;
            float* Cc; int ldc, cc;
            if (colg < split) { Cc = C0; ldc = ld0; cc = colg; }
            else              { Cc = C1; ldc = ld1; cc = colg - split; }
            int row0 = m0 + warp_m * 32 + i * 16 + gq;
            *(float2*)&Cc[(size_t)row0 * ldc + cc] =
                make_float2(acc[i][j][0] + bz0, acc[i][j][1] + bz1);
            *(float2*)&Cc[(size_t)(row0 + 8) * ldc + cc] =
                make_float2(acc[i][j][2] + bz0, acc[i][j][3] + bz1);
        }
    }
}

// ===================== fused att: logits + softmax + W (bf16 triple) ========
// One block per n (128 blocks), 256 threads. Dynamic smem ~106KB.
__global__ __launch_bounds__(256) void fused_att_kernel(
    const float* __restrict__ S, const float* __restrict__ assign,
    const void* __restrict__ mask, const float* __restrict__ rel_bias,
    __nv_bfloat16* __restrict__ W3)
{
    extern __shared__ float sm[];
    float* Ss   = sm;                         // [128][132]
    float* AsT  = Ss + 128 * 132;             // [17][132] (+1 guard row)
    float* Atmp = AsT + 18 * 132;             // [2176]
    float* Ls   = Atmp + 2176;                // [128][20]
    float* Ps   = Ls + 128 * 20;              // [128][20]
    float* rb   = Ps + 128 * 20;              // [136]
    int*   mk   = (int*)(rb + 136);           // [17]
    const int t = threadIdx.x;
    const int n = blockIdx.x;

    const float* arow = assign + (size_t)n * (kN * kR);
    for (int i = t; i < 544; i += 256)
        *(float4*)&Atmp[i * 4] = *(const float4*)&arow[i * 4];
    if (t < 136) rb[t] = rel_bias[t];
    if (t < 17) {
        int mode = g_mask_mode;
        int idx = n * kR + t;
        bool m_;
        if (mode == 0)      m_ = ((const int*)mask)[idx] != 0;
        else if (mode == 1) m_ = ((const float*)mask)[idx] != 0.f;
        else                m_ = ((const unsigned char*)mask)[idx] != 0;
        mk[t] = m_ ? 1 : 0;
    }
    {
        const int bh = t >> 1, half = t & 1;
        const float* srow = S + ((size_t)bh * kN + n) * kN + half * 64;
        float* drow = Ss + bh * 132 + half * 64;
#pragma unroll
        for (int g = 0; g < 16; g++)
            *(float4*)&drow[g * 4] = *(const float4*)&srow[g * 4];
    }
    __syncthreads();
    for (int i = t; i < kN * kR; i += 256) {
        int m = i / kR, r = i - m * kR;
        AsT[r * 132 + m] = Atmp[i];
    }
    __syncthreads();

    // logits: L[bh][r] = sum_m Ss[bh][m] * AsT[r][m]
    {
        const int bh = t >> 1, rh = t & 1;
        const int r0 = rh ? 9 : 0;
        const int nr = rh ? 8 : 9;
        float pr[9];
#pragma unroll
        for (int j = 0; j < 9; j++) pr[j] = 0.f;
        const float* srow = Ss + bh * 132;
        for (int mg = 0; mg < 32; mg++) {
            float4 s = *(const float4*)&srow[mg * 4];
#pragma unroll
            for (int j = 0; j < 9; j++) {
                float4 a = *(const float4*)&AsT[(r0 + j) * 132 + mg * 4];
                pr[j] += s.x * a.x + s.y * a.y + s.z * a.z + s.w * a.w;
            }
        }
        const int h = bh & 7;
        for (int j = 0; j < nr; j++) {
            int r = r0 + j;
            Ls[bh * 20 + r] = mk[r] ? neg_inf() : (pr[j] + rb[h * kR + r]);
        }
    }
    __syncthreads();

    if (t < 128) {
        float mx = neg_inf();
#pragma unroll
        for (int r = 0; r < kR; r++) mx = fmaxf(mx, Ls[t * 20 + r]);
        float s = 0.f;
#pragma unroll
        for (int r = 0; r < kR; r++) {
            float e = __expf(Ls[t * 20 + r] - mx);
            Ps[t * 20 + r] = e; s += e;
        }
        float inv = 1.f / s;
#pragma unroll
        for (int r = 0; r < kR; r++) Ps[t * 20 + r] *= inv;
    }
    __syncthreads();

    // W[bh][m] = sum_r P[bh][r] * AsT[r][m], emit hi|lo|hi triple (384 elems)
    {
        const int bh = t >> 1, half = t & 1;
        float p[17];
#pragma unroll
        for (int r = 0; r < kR; r++) p[r] = Ps[bh * 20 + r];
        __nv_bfloat16* wrow = W3 + ((size_t)bh * kN + n) * kKm + half * 64;
        for (int mg = 0; mg < 16; mg++) {
            const int m = half * 64 + mg * 4;
            float ax = 0.f, ay = 0.f, az = 0.f, aw = 0.f;
#pragma unroll
            for (int r = 0; r < kR; r++) {
                float4 a = *(const float4*)&AsT[r * 132 + m];
                ax += p[r] * a.x; ay += p[r] * a.y;
                az += p[r] * a.z; aw += p[r] * a.w;
            }
            __nv_bfloat16 h0 = __float2bfloat16(ax), h1 = __float2bfloat16(ay);
            __nv_bfloat16 h2 = __float2bfloat16(az), h3 = __float2bfloat16(aw);
            __nv_bfloat16 l0 = __float2bfloat16(ax - __bfloat162float(h0));
            __nv_bfloat16 l1 = __float2bfloat16(ay - __bfloat162float(h1));
            __nv_bfloat16 l2 = __float2bfloat16(az - __bfloat162float(h2));
            __nv_bfloat16 l3 = __float2bfloat16(aw - __bfloat162float(h3));
            uint32_t hp0 = pack_bf2(h0, h1), hp1 = pack_bf2(h2, h3);
            uint32_t lp0 = pack_bf2(l0, l1), lp1 = pack_bf2(l2, l3);
            uint32_t* o0 = (uint32_t*)(wrow + mg * 4);
            uint32_t* o1 = (uint32_t*)(wrow + 128 + mg * 4);
            uint32_t* o2 = (uint32_t*)(wrow + 256 + mg * 4);
            o0[0] = hp0; o0[1] = hp1;
            o1[0] = lp0; o1[1] = lp1;
            o2[0] = hp0; o2[1] = hp1;
        }
    }
}

// ===================== av mma: O[n][d] = W3 @ yv3^T per (b,h) ===============
// A = W3[bh] (128 x 384 elems = 768B rows), B = yv3[bh] (64 x 768B rows).
__global__ __launch_bounds__(256) void av_mma_kernel(
    const __nv_bfloat16* __restrict__ W3, const __nv_bfloat16* __restrict__ yv3,
    __nv_bfloat16* __restrict__ AO)
{
    __shared__ __align__(16) char smem[2][12288];
    const int tid = threadIdx.x, wid = tid >> 5, lane = tid & 31;
    const int bh = blockIdx.x;
    const int warp_m = wid >> 1, warp_n = wid & 1;
    const char* Ag = (const char*)W3  + (size_t)bh * kN  * (kKm * 2);
    const char* Bg = (const char*)yv3 + (size_t)bh * kHD * (kKm * 2);
    const int lr = tid >> 2, lc = tid & 3;
    const uint32_t lso  = (uint32_t)(lr * 64 + ((lc ^ (lr & 3)) << 4));
    const uint32_t lso2 = (uint32_t)((lr + 64) * 64 + ((lc ^ ((lr + 64) & 3)) << 4));
    uint32_t sbase = smem_u32(&smem[0][0]);

    auto stage_load = [&](int st, int k0b) {
        uint32_t sA = sbase + st * 12288;
        uint32_t sB = sA + 8192;
        const char* a0 = Ag + (size_t)lr * 768 + k0b + lc * 16;
        cp_async16(sA + lso,  a0);
        cp_async16(sA + lso2, a0 + (size_t)64 * 768);
        cp_async16(sB + lso,  Bg + (size_t)lr * 768 + k0b + lc * 16);
    };

    float acc[2][4][4];
#pragma unroll
    for (int i = 0; i < 2; i++)
#pragma unroll
        for (int j = 0; j < 4; j++)
#pragma unroll
            for (int t = 0; t < 4; t++) acc[i][j][t] = 0.f;

    stage_load(0, 0);
    cp_commit();

    const int a_row = warp_m * 32 + (lane & 15);
    const int a_chsel = lane >> 4;
    const int b_mi = lane >> 3;
    const int b_row = warp_n * 32 + ((b_mi >> 1) << 3) + (lane & 7);
    const int b_chsel = b_mi & 1;

    for (int it = 0; it < 12; it++) {
        cp_wait0();
        __syncthreads();
        if (it + 1 < 12) { stage_load((it + 1) & 1, (it + 1) * 64); cp_commit(); }

        const uint32_t sA = sbase + (it & 1) * 12288;
        const uint32_t sB = sA + 8192;
#pragma unroll
        for (int kk = 0; kk < 2; kk++) {
            uint32_t a[2][4];
#pragma unroll
            for (int i = 0; i < 2; i++) {
                int r = a_row + i * 16;
                int ch = 2 * kk + a_chsel;
                ldsm_x4(a[i], sA + r * 64 + ((ch ^ (r & 3)) << 4));
            }
            uint32_t b[4][2];
#pragma unroll
            for (int g = 0; g < 2; g++) {
                int r = b_row + g * 16;
                int ch = 2 * kk + b_chsel;
                uint32_t rr[4];
                ldsm_x4(rr, sB + r * 64 + ((ch ^ (r & 3)) << 4));
                b[2 * g][0] = rr[0]; b[2 * g][1] = rr[1];
                b[2 * g + 1][0] = rr[2]; b[2 * g + 1][1] = rr[3];
            }
#pragma unroll
            for (int i = 0; i < 2; i++)
#pragma unroll
                for (int j = 0; j < 4; j++)
                    mma16816(acc[i][j], a[i], b[j]);
        }
        __syncthreads();
    }

    // epilogue -> AO triple (hi|lo|hi along 1536)
    const int gq = lane >> 2, t4 = lane & 3;
    const int b_ = bh >> 3, h_ = bh & 7;
#pragma unroll
    for (int i = 0; i < 2; i++) {
#pragma unroll
        for (int j = 0; j < 4; j++) {
            const int d = warp_n * 32 + j * 8 + t4 * 2;
            const int c = h_ * kHD + d;
#pragma unroll
            for (int rr = 0; rr < 2; rr++) {
                const int nrow = warp_m * 32 + i * 16 + gq + rr * 8;
                const float f0 = acc[i][j][rr * 2], f1 = acc[i][j][rr * 2 + 1];
                __nv_bfloat16 h0 = __float2bfloat16(f0), h1 = __float2bfloat16(f1);
                __nv_bfloat16 l0 = __float2bfloat16(f0 - __bfloat162float(h0));
                __nv_bfloat16 l1 = __float2bfloat16(f1 - __bfloat162float(h1));
                __nv_bfloat16* base = AO + (size_t)(b_ * kN + nrow) * kKp + c;
                *(uint32_t*)(base)        = pack_bf2(h0, h1);
                *(uint32_t*)(base + 512)  = pack_bf2(l0, l1);
                *(uint32_t*)(base + 1024) = pack_bf2(h0, h1);
            }
        }
    }
}

// ===================== launch =====================
extern "C" void kernel_launch(void* const* d_in, const int* in_sizes, int n_in,
                              void* d_out, int out_size)
{
    const float* x        = (const float*)d_in[0];
    const float* assign   = (const float*)d_in[1];
    const void*  mask     = d_in[2];
    const float* q_w      = (const float*)d_in[3];
    const float* kv_w     = (const float*)d_in[4];
    const float* rel_bias = (const float*)d_in[5];
    const float* proj_w   = (const float*)d_in[6];
    const float* proj_b   = (const float*)d_in[7];

    float *S;
    __nv_bfloat16 *Ax, *Bqkv, *Bproj, *AO, *qbf, *kbf, *W3, *yv3;
    cudaGetSymbolAddress((void**)&S,   g_S);
    cudaGetSymbolAddress((void**)&Ax,    g_Ax);
    cudaGetSymbolAddress((void**)&Bqkv,  g_Bqkv);
    cudaGetSymbolAddress((void**)&Bproj, g_Bproj);
    cudaGetSymbolAddress((void**)&AO,    g_AO);
    cudaGetSymbolAddress((void**)&qbf,   g_qbf);
    cudaGetSymbolAddress((void**)&kbf,   g_kbf);
    cudaGetSymbolAddress((void**)&W3,    g_W3);
    cudaGetSymbolAddress((void**)&yv3,   g_yv3);

    const int ATT_SMEM = (128 * 132 + 18 * 132 + 2176 + 128 * 20 * 2 + 136 + 17 + 8) * 4;
    cudaFuncSetAttribute(fused_att_kernel,
                         cudaFuncAttributeMaxDynamicSharedMemorySize, ATT_SMEM);

    // 1. input hi/lo splits + mask probe
    convert_all_kernel<<<4097, 128>>>(x, q_w, kv_w, proj_w, mask, Ax, Bqkv, Bproj);

    // 2. fused q/kv projection -> qbf/kbf triples + yv3 triple
    mma_gemm_t<3072, 48, 1><<<dim3(12, 16), 256>>>(
        Ax, Bqkv, nullptr, nullptr, nullptr, 0, 0, 0, qbf, kbf, yv3);

    // 3. S = 0.125 * q@k^T per (b,h)
    mma_gemm_t<384, 6, 2><<<dim3(128, 1), 256>>>(
        qbf, kbf, S, nullptr, nullptr, 0, 0, 0, nullptr, nullptr, nullptr);

    // 4. fused logits + softmax + W (emits W3 triple)
    fused_att_kernel<<<128, 256, ATT_SMEM>>>(S, assign, mask, rel_bias, W3);

    // 5. O = W @ yv per (b,h) on tensor cores (emits AO triple)
    av_mma_kernel<<<128, 256>>>(W3, yv3, AO);

    // 6. out-proj: AO @ Bproj^T + bias
    mma_gemm_t<3072, 48, 0><<<dim3(4, 16), 256>>>(
        AO, Bproj, (float*)d_out, (float*)d_out, proj_b, 1 << 30, kC, kC,
        nullptr, nullptr, nullptr);
}